// round 10
// baseline (speedup 1.0000x reference)
#include <cuda_runtime.h>
#include <cstdint>

#define BATCH 4
#define SEQ   2048
#define DMODEL 1024

// Scratch (device globals — no cudaMalloc allowed)
__device__ float g_QKV[(size_t)3 * BATCH * SEQ * DMODEL];   // 96 MB (Q,K planes used)
__device__ float g_P  [(size_t)BATCH * SEQ * SEQ];          // 64 MB (exp-scores)
__device__ float g_AO [(size_t)BATCH * SEQ * DMODEL];       // 32 MB
__device__ float g_X  [(size_t)BATCH * SEQ * DMODEL];       // 32 MB (tf32-rounded x)
__device__ float g_W  [(size_t)4 * DMODEL * DMODEL];        // 16 MB (WqT,WkT,WvT,WoT rounded)
__device__ float g_VT [(size_t)BATCH * SEQ * DMODEL];       // 32 MB (V transposed per batch)
__device__ float g_RS [(size_t)BATCH * SEQ];                // 32 KB (1/rowsum)

__device__ __forceinline__ uint32_t f2tf32(float x) {
    uint32_t r;
    asm("cvt.rna.tf32.f32 %0, %1;" : "=r"(r) : "f"(x));
    return r;
}
__device__ __forceinline__ float rtf(float x) { return __uint_as_float(f2tf32(x)); }

__device__ __forceinline__ void mma8(float c[4], const uint32_t a[4], const uint32_t b[2]) {
    asm("mma.sync.aligned.m16n8k8.row.col.f32.tf32.tf32.f32 "
        "{%0,%1,%2,%3}, {%4,%5,%6,%7}, {%8,%9}, {%0,%1,%2,%3};\n"
        : "+f"(c[0]), "+f"(c[1]), "+f"(c[2]), "+f"(c[3])
        : "r"(a[0]), "r"(a[1]), "r"(a[2]), "r"(a[3]), "r"(b[0]), "r"(b[1]));
}

__device__ __forceinline__ void cpa16s(uint32_t dst, const float* src) {
    asm volatile("cp.async.cg.shared.global [%0], [%1], 16;\n" :: "r"(dst), "l"(src));
}

__device__ __forceinline__ void ldmx4s(uint32_t r[4], uint32_t addr) {
    asm volatile("ldmatrix.sync.aligned.m8n8.x4.shared.b16 {%0,%1,%2,%3}, [%4];"
        : "=r"(r[0]), "=r"(r[1]), "=r"(r[2]), "=r"(r[3]) : "r"(addr));
}

// SW128-style XOR swizzle on byte offsets (16B granular)
__device__ __forceinline__ uint32_t sw128(uint32_t off) {
    return off ^ ((off >> 3) & 0x70u);
}

// ---------------- pre-pass kernels ----------------

__global__ void round_tf32(const float4* __restrict__ in, float4* __restrict__ out, int n4)
{
    int i = blockIdx.x * blockDim.x + threadIdx.x;
    if (i < n4) {
        float4 v = in[i];
        v.x = rtf(v.x); v.y = rtf(v.y); v.z = rtf(v.z); v.w = rtf(v.w);
        out[i] = v;
    }
}

// Fused 4-weight transpose+round: z selects source W; out plane z.
__global__ void transpose_round_w(const float* __restrict__ W0, const float* __restrict__ W1,
                                  const float* __restrict__ W2, const float* __restrict__ W3,
                                  float* __restrict__ out)
{
    __shared__ float tile[32][33];
    const int z = blockIdx.z;
    const float* in = (z == 0) ? W0 : (z == 1) ? W1 : (z == 2) ? W2 : W3;
    out += (size_t)z * DMODEL * DMODEL;
    const int bx = blockIdx.x * 32;
    const int by = blockIdx.y * 32;
    const int tx = threadIdx.x, ty = threadIdx.y;
    #pragma unroll
    for (int i = 0; i < 32; i += 8)
        tile[ty + i][tx] = in[(size_t)(by + ty + i) * DMODEL + bx + tx];
    __syncthreads();
    #pragma unroll
    for (int i = 0; i < 32; i += 8)
        out[(size_t)(bx + ty + i) * DMODEL + by + tx] = rtf(tile[tx][ty + i]);
}

// 1/rowsum over 2048-wide rows of P (deterministic tree reduction).
__global__ void rowsum_inv(const float* __restrict__ P, float* __restrict__ inv)
{
    const float* p = P + (size_t)blockIdx.x * 2048;
    const int t = threadIdx.x, lane = t & 31, wid = t >> 5;
    __shared__ float red[8];
    float4 v0 = ((const float4*)p)[t];
    float4 v1 = ((const float4*)p)[t + 256];
    float s = v0.x + v0.y + v0.z + v0.w + v1.x + v1.y + v1.z + v1.w;
    #pragma unroll
    for (int o = 16; o; o >>= 1) s += __shfl_xor_sync(0xffffffffu, s, o);
    if (lane == 0) red[wid] = s;
    __syncthreads();
    if (t == 0) {
        float bs = red[0];
        #pragma unroll
        for (int w = 1; w < 8; w++) bs += red[w];
        inv[blockIdx.x] = 1.0f / bs;
    }
}

// ---------------- NT TF32 GEMM: C[M,N] = A[M,K] * B[N,K]^T ----------------
// CTA tile 128x128x32, 4 warps (2x2), warp tile 64x64, 3-stage cp.async,
// XOR-swizzled smem, ldmatrix fragments (register double-buffered).
//   TRIPLE: blockIdx.z selects B among {B0,B1,B2}; z==2 writes transposed to vt.
//   mask: epilogue exp(v*scale) masked->0, tf32-rounded (scores path)
//   rowinv: multiply row r by rowinv[bz*M+r] before rounding (PV path)
//   roundC: round outputs to tf32.
template<bool TRIPLE>
__global__ __launch_bounds__(128, 2)
void gemm_nt(const float* __restrict__ A, const float* __restrict__ B0,
             const float* __restrict__ B1, const float* __restrict__ B2,
             float* __restrict__ C, int M, int N, int K,
             size_t sA, size_t sB, size_t sC,
             const unsigned char* __restrict__ mask, float scale, int roundC,
             const float* __restrict__ rowinv, float* __restrict__ vt)
{
    constexpr int BK = 32;
    constexpr uint32_t TILE_B = 128u * 128u;     // 16 KB per operand tile
    constexpr uint32_t STG_B  = 2u * TILE_B;     // 32 KB per stage
    constexpr int NSTAGE = 3;

    extern __shared__ float smf[];
    __shared__ int mask_is_int32;

    const int bz = blockIdx.z;
    const float* B;
    if (TRIPLE) {
        B = (bz == 0) ? B0 : (bz == 1 ? B1 : B2);
        C += (size_t)bz * sC;
    } else {
        B = B0 + (size_t)bz * sB;
        A += (size_t)bz * sA;
        C += (size_t)bz * sC;
    }

    const int bm = blockIdx.y * 128;
    const int bn = blockIdx.x * 128;
    const int t    = threadIdx.x;
    const int lane = t & 31;
    const int wid  = t >> 5;
    const int wm   = wid >> 1;        // 0..1 (M)
    const int wn   = wid & 1;         // 0..1 (N)
    const int g    = lane >> 2;       // 0..7
    const int tig  = lane & 3;        // 0..3

    uint32_t smem_base = (uint32_t)__cvta_generic_to_shared(smf);
    smem_base = (smem_base + 127u) & ~127u;

    if (mask && t == 0) {
        int is_int = 1;
        #pragma unroll 4
        for (int i = 0; i < 256; i++)
            if ((i & 3) != 0 && mask[i] != 0) is_int = 0;
        mask_is_int32 = is_int;
    }

    float acc[4][8][4];
    #pragma unroll
    for (int i = 0; i < 4; i++)
        #pragma unroll
        for (int j = 0; j < 8; j++)
            #pragma unroll
            for (int r = 0; r < 4; r++) acc[i][j][r] = 0.f;

    const int nkt = K / BK;

    auto issue = [&](int kt) {
        const uint32_t abase = smem_base + (uint32_t)(kt % NSTAGE) * STG_B;
        const uint32_t bbase = abase + TILE_B;
        const float* gA = A + (size_t)bm * K + (size_t)kt * BK;
        const float* gB = B + (size_t)bn * K + (size_t)kt * BK;
        #pragma unroll
        for (int i = 0; i < 8; i++) {
            const int chunk = t + i * 128;          // 0..1023
            const int row = chunk >> 3, kc = chunk & 7;
            const uint32_t sw = sw128((uint32_t)(row * 128 + kc * 16));
            cpa16s(abase + sw, gA + (size_t)row * K + kc * 4);
            cpa16s(bbase + sw, gB + (size_t)row * K + kc * 4);
        }
        asm volatile("cp.async.commit_group;\n");
    };

    issue(0); issue(1);

    const int a_row = (lane & 15);
    const int a_kof = (lane >> 4) << 2;
    const int b_row = (lane & 7) + ((lane & 16) >> 1);
    const int b_kof = (lane & 8) >> 1;

    uint32_t af[2][4][4];
    uint32_t bf[2][8][2];

    for (int kt = 0; kt < nkt; ++kt) {
        if (kt + 1 < nkt) asm volatile("cp.async.wait_group 1;\n");
        else              asm volatile("cp.async.wait_group 0;\n");
        __syncthreads();

        const uint32_t abase = smem_base + (uint32_t)(kt % NSTAGE) * STG_B;
        const uint32_t bbase = abase + TILE_B;

        auto ldfrag = [&](int ks, int buf) {
            const int k0 = ks * 8;
            #pragma unroll
            for (int i = 0; i < 4; i++) {
                const int rb = wm * 64 + i * 16;
                const uint32_t off = (uint32_t)((rb + a_row) * 128 + (k0 + a_kof) * 4);
                ldmx4s(af[buf][i], abase + sw128(off));
            }
            #pragma unroll
            for (int jp = 0; jp < 4; jp++) {
                uint32_t bq[4];
                const int nb = wn * 64 + jp * 16;
                const uint32_t off = (uint32_t)((nb + b_row) * 128 + (k0 + b_kof) * 4);
                ldmx4s(bq, bbase + sw128(off));
                bf[buf][jp * 2][0]     = bq[0];
                bf[buf][jp * 2][1]     = bq[1];
                bf[buf][jp * 2 + 1][0] = bq[2];
                bf[buf][jp * 2 + 1][1] = bq[3];
            }
        };

        ldfrag(0, 0);
        if (kt + 2 < nkt) issue(kt + 2);

        #pragma unroll
        for (int ks = 0; ks < 4; ++ks) {
            const int cur = ks & 1;
            if (ks < 3) ldfrag(ks + 1, cur ^ 1);
            #pragma unroll
            for (int i = 0; i < 4; i++)
                #pragma unroll
                for (int j = 0; j < 8; j++)
                    mma8(acc[i][j], af[cur][i], bf[cur][j]);
        }
    }

    // ---- epilogue ----
    if (TRIPLE && bz == 2) {
        // V plane: write transposed (VT[b][d][s]) via smem staging; skip C store.
        __syncthreads();                 // all warps done reading stage smem
        float* ts = smf;                 // [128][129] row-major
        #pragma unroll
        for (int i = 0; i < 4; i++) {
            const int rl = wm * 64 + i * 16 + g;
            #pragma unroll
            for (int j = 0; j < 8; j++) {
                const int cl = wn * 64 + j * 8 + tig * 2;
                ts[rl * 129 + cl]           = rtf(acc[i][j][0]);
                ts[rl * 129 + cl + 1]       = rtf(acc[i][j][1]);
                ts[(rl + 8) * 129 + cl]     = rtf(acc[i][j][2]);
                ts[(rl + 8) * 129 + cl + 1] = rtf(acc[i][j][3]);
            }
        }
        __syncthreads();
        const int b     = bm >> 11;          // bm / 2048
        const int sbase = bm & 2047;
        float* vtp = vt + (size_t)b * ((size_t)SEQ * DMODEL);
        #pragma unroll 4
        for (int i = 0; i < 32; i++) {
            const int c = wid * 32 + i;      // local d
            float* dstrow = vtp + (size_t)(bn + c) * SEQ + sbase;
            #pragma unroll
            for (int ch = 0; ch < 4; ch++) {
                const int s = lane + ch * 32;
                dstrow[s] = ts[s * 129 + c];
            }
        }
        return;
    }

    #pragma unroll
    for (int i = 0; i < 4; i++) {
        const int r0 = bm + wm * 64 + i * 16 + g;
        float ri0 = 1.f, ri1 = 1.f;
        if (rowinv) {
            ri0 = rowinv[(size_t)bz * M + r0];
            ri1 = rowinv[(size_t)bz * M + r0 + 8];
        }
        #pragma unroll
        for (int j = 0; j < 8; j++) {
            const int c0 = bn + wn * 64 + j * 8 + tig * 2;
            float v0 = acc[i][j][0], v1 = acc[i][j][1];
            float v2 = acc[i][j][2], v3 = acc[i][j][3];
            if (mask) {
                // scores path: v -> exp(v*scale) (masked -> 0), tf32-rounded
                const size_t base = (size_t)bz * (size_t)M * N + (size_t)r0 * N;
                int m00, m01, m10, m11;
                if (mask_is_int32) {
                    const int* mi = (const int*)mask;
                    int2 ma = *(const int2*)&mi[base + c0];
                    int2 mb = *(const int2*)&mi[base + (size_t)8 * N + c0];
                    m00 = ma.x; m01 = ma.y; m10 = mb.x; m11 = mb.y;
                } else {
                    m00 = mask[base + c0];                   m01 = mask[base + c0 + 1];
                    m10 = mask[base + (size_t)8 * N + c0];   m11 = mask[base + (size_t)8 * N + c0 + 1];
                }
                v0 = m00 ? rtf(__expf(v0 * scale)) : 0.f;
                v1 = m01 ? rtf(__expf(v1 * scale)) : 0.f;
                v2 = m10 ? rtf(__expf(v2 * scale)) : 0.f;
                v3 = m11 ? rtf(__expf(v3 * scale)) : 0.f;
            } else {
                if (rowinv) { v0 *= ri0; v1 *= ri0; v2 *= ri1; v3 *= ri1; }
                if (roundC) { v0 = rtf(v0); v1 = rtf(v1); v2 = rtf(v2); v3 = rtf(v3); }
            }
            float2 w0 = {v0, v1}, w1 = {v2, v3};
            *(float2*)&C[(size_t)r0 * N + c0]       = w0;
            *(float2*)&C[(size_t)(r0 + 8) * N + c0] = w1;
        }
    }
}

// ---------------- host ----------------

extern "C" void kernel_launch(void* const* d_in, const int* in_sizes, int n_in,
                              void* d_out, int out_size)
{
    const float*         x    = (const float*)d_in[0];
    const unsigned char* mask = (const unsigned char*)d_in[1];
    const float*         Wq   = (const float*)d_in[2];
    const float*         Wk   = (const float*)d_in[3];
    const float*         Wv   = (const float*)d_in[4];
    const float*         Wo   = (const float*)d_in[5];
    float*               out  = (float*)d_out;

    float *QKV, *P, *AO, *X, *W, *VT, *RS;
    cudaGetSymbolAddress((void**)&QKV, g_QKV);
    cudaGetSymbolAddress((void**)&P,   g_P);
    cudaGetSymbolAddress((void**)&AO,  g_AO);
    cudaGetSymbolAddress((void**)&X,   g_X);
    cudaGetSymbolAddress((void**)&W,   g_W);
    cudaGetSymbolAddress((void**)&VT,  g_VT);
    cudaGetSymbolAddress((void**)&RS,  g_RS);

    const size_t pstride = (size_t)BATCH * SEQ * DMODEL;   // full Q/K/V plane
    const size_t bstride = (size_t)SEQ * DMODEL;           // per-batch plane
    const size_t wsz = (size_t)DMODEL * DMODEL;
    float* WqT = W;
    float* WkT = W + wsz;
    float* WvT = W + 2 * wsz;
    float* Q  = QKV;
    float* Kp = QKV + pstride;
    float* WoT = W + 3 * wsz;

    // --- pre-pass: round x; fused transpose+round of all weights ---
    {
        const int xe4 = (int)(pstride / 4);
        round_tf32<<<(xe4 + 255) / 256, 256>>>((const float4*)x, (float4*)X, xe4);
        dim3 tb(32, 8);
        dim3 tgw(DMODEL / 32, DMODEL / 32, 4);
        transpose_round_w<<<tgw, tb>>>(Wq, Wk, Wv, Wo, W);
    }

    const int smemB = 3 * 32768 + 128;   // 3 stages + alignment slack
    cudaFuncSetAttribute(gemm_nt<true>,
                         cudaFuncAttributeMaxDynamicSharedMemorySize, smemB);
    cudaFuncSetAttribute(gemm_nt<false>,
                         cudaFuncAttributeMaxDynamicSharedMemorySize, smemB);

    const int MS = BATCH * SEQ;   // 8192
    dim3 blk(128);

    // QKV projections fused: z in {Q,K,V}; V written transposed into VT
    dim3 gq(DMODEL / 128, MS / 128, 3);
    gemm_nt<true><<<gq, blk, smemB>>>(
        X, WqT, WkT, WvT, QKV, MS, DMODEL, DMODEL, 0, 0, pstride,
        nullptr, 1.f, 1, nullptr, VT);

    // P = exp(Q K^T / 32) masked->0 (tf32-rounded), no softmax kernel
    dim3 gs(SEQ / 128, SEQ / 128, BATCH);
    gemm_nt<false><<<gs, blk, smemB>>>(
        Q, Kp, nullptr, nullptr, P, SEQ, SEQ, DMODEL,
        bstride, bstride, (size_t)SEQ * SEQ, mask, 0.03125f, 0, nullptr, nullptr);

    // 1/rowsum of P
    rowsum_inv<<<BATCH * SEQ, 256>>>(P, RS);

    // attn_out = (P V) * rowinv  (B = VT[b] is [DMODEL rows, SEQ cols] K-major)
    dim3 gv(DMODEL / 128, SEQ / 128, BATCH);
    gemm_nt<false><<<gv, blk, smemB>>>(
        P, VT, nullptr, nullptr, AO, SEQ, DMODEL, SEQ,
        (size_t)SEQ * SEQ, bstride, bstride, nullptr, 1.f, 1, RS, nullptr);

    // output projection: out[m,n] = AO[m,k] * WoT[n,k]
    dim3 go(DMODEL / 128, MS / 128, 1);
    gemm_nt<false><<<go, blk, smemB>>>(
        AO, WoT, nullptr, nullptr, out, MS, DMODEL, DMODEL, 0, 0, 0,
        nullptr, 1.f, 0, nullptr, nullptr);
}